// round 2
// baseline (speedup 1.0000x reference)
#include <cuda_runtime.h>
#include <math_constants.h>

// YOLO head decode:
//   out[r, :] = {x, y, w, h, class_idx, conf}  if conf > 0.5 else zeros
// Row order: small(104) rows, middle(208), large(416); within a level
// r = (i*S + j)*3 + a  with x using i, y using j (matches reference broadcast).

static constexpr int NR_S = 104 * 104 * 3;   //  32448
static constexpr int NR_M = 208 * 208 * 3;   // 129792
static constexpr int NR_L = 416 * 416 * 3;   // 519168
static constexpr int NR_TOT = NR_S + NR_M + NR_L;  // 681408

__global__ __launch_bounds__(256) void yolo_decode_kernel(
    const float* __restrict__ ps, const float* __restrict__ pm,
    const float* __restrict__ pl, const float* __restrict__ anch,
    float* __restrict__ out)
{
    const unsigned gwarp = (blockIdx.x * 256u + threadIdx.x) >> 5;
    const int lane = threadIdx.x & 31;
    if (gwarp >= (unsigned)NR_TOT) return;

    const float* p;
    unsigned r, S3;
    float fS;
    int dect;
    if (gwarp < (unsigned)NR_S) {
        p = ps; r = gwarp;                 fS = 104.f; S3 = 312u;  dect = 3;
    } else if (gwarp < (unsigned)(NR_S + NR_M)) {
        p = pm; r = gwarp - NR_S;          fS = 208.f; S3 = 624u;  dect = 4;
    } else {
        p = pl; r = gwarp - (NR_S + NR_M); fS = 416.f; S3 = 1248u; dect = 5;
    }

    const float* row = p + (size_t)r * 85u;
    float* orow = out + (size_t)gwarp * 6u;

    // --- conf gate: ~69% of rows take this path, touching 1 sector only ---
    const float conf = __ldg(row);
    if (!(conf > 0.5f)) {
        if (lane < 6) orow[lane] = 0.0f;
        return;
    }

    // --- heavy path: read the full 85-channel row, lane-strided (coalesced) ---
    const float v0 = __ldg(row + lane);           // channels lane      (0..31)
    const float v1 = __ldg(row + 32 + lane);      // channels lane+32   (32..63)
    const float v2 = (lane < 21) ? __ldg(row + 64 + lane) : 0.0f;  // 64..84

    // per-lane argmax over class channels (>= 5); local candidates are in
    // increasing channel order so strict '>' keeps the first max
    float bv = -CUDART_INF_F;
    int   bc = 0x7fffffff;
    if (lane >= 5)               { bv = v0; bc = lane; }
    if (v1 > bv)                 { bv = v1; bc = lane + 32; }
    if (lane < 21 && v2 > bv)    { bv = v2; bc = lane + 64; }

    // butterfly reduce; on ties prefer the smaller channel (first-max).
    // All lanes converge to the same (bv, bc) -> no extra broadcast needed.
    #pragma unroll
    for (int off = 16; off; off >>= 1) {
        float ov = __shfl_xor_sync(0xffffffffu, bv, off);
        int   oc = __shfl_xor_sync(0xffffffffu, bc, off);
        if (ov > bv || (ov == bv && oc < bc)) { bv = ov; bc = oc; }
    }
    const int best = bc;  // channel index of argmax (>= 5)

    // broadcast tx,ty,tw,th (channels 1..4, owned by lanes 1..4 in v0)
    const float tx = __shfl_sync(0xffffffffu, v0, 1);
    const float ty = __shfl_sync(0xffffffffu, v0, 2);
    const float tw = __shfl_sync(0xffffffffu, v0, 3);
    const float th = __shfl_sync(0xffffffffu, v0, 4);

    if (lane < 6) {
        // grid coordinates
        const unsigned i  = r / S3;          // axis-0 index -> x offset
        const unsigned jA = r - i * S3;
        const unsigned j  = jA / 3u;         // axis-1 index -> y offset
        const unsigned a  = jA - j * 3u;     // anchor index

        const float invS = 1.0f / fS;
        const float aw = __ldg(anch + dect * 6 + a * 2 + 0) * (1.0f / 416.0f);
        const float ah = __ldg(anch + dect * 6 + a * 2 + 1) * (1.0f / 416.0f);

        const float sx = 1.0f / (1.0f + __expf(-tx));
        const float sy = 1.0f / (1.0f + __expf(-ty));
        const float x = (sx + (float)i) * invS;
        const float y = (sy + (float)j) * invS;
        const float w = __expf(tw) * aw;
        const float h = __expf(th) * ah;

        float res;
        if      (lane == 0) res = x;
        else if (lane == 1) res = y;
        else if (lane == 2) res = w;
        else if (lane == 3) res = h;
        else if (lane == 4) res = (float)(best - 5);
        else                res = conf;
        orow[lane] = res;
    }
}

extern "C" void kernel_launch(void* const* d_in, const int* in_sizes, int n_in,
                              void* d_out, int out_size) {
    // identify inputs by element count (robust to metadata ordering)
    const float *ps = nullptr, *pm = nullptr, *pl = nullptr, *anch = nullptr;
    for (int k = 0; k < n_in; k++) {
        switch (in_sizes[k]) {
            case 104 * 104 * 3 * 85: ps   = (const float*)d_in[k]; break;
            case 208 * 208 * 3 * 85: pm   = (const float*)d_in[k]; break;
            case 416 * 416 * 3 * 85: pl   = (const float*)d_in[k]; break;
            case 36:                 anch = (const float*)d_in[k]; break;
            default: break;
        }
    }
    const int warps_per_block = 8;  // 256 threads
    const int blocks = (NR_TOT + warps_per_block - 1) / warps_per_block;
    yolo_decode_kernel<<<blocks, 256>>>(ps, pm, pl, anch, (float*)d_out);
}

// round 3
// speedup vs baseline: 1.8966x; 1.8966x over previous
#include <cuda_runtime.h>
#include <math_constants.h>

// YOLO head decode, v2: thread-per-row conf scan + in-warp cooperative decode.
//   out[r, :] = {x, y, w, h, class_idx, conf}  if conf > 0.5 else zeros
// Output is pre-zeroed by cudaMemsetAsync; kernel only writes passing rows.

static constexpr int NR_S = 104 * 104 * 3;   //  32448  (mult of 32)
static constexpr int NR_M = 208 * 208 * 3;   // 129792
static constexpr int NR_L = 416 * 416 * 3;   // 519168
static constexpr int NR_TOT = NR_S + NR_M + NR_L;  // 681408 (mult of 32)

__device__ __forceinline__ unsigned mono_u32(float f) {
    // monotonic order-preserving float -> uint transform
    unsigned u = __float_as_uint(f);
    return (u & 0x80000000u) ? ~u : (u | 0x80000000u);
}

__global__ __launch_bounds__(256) void yolo_decode_v2(
    const float* __restrict__ ps, const float* __restrict__ pm,
    const float* __restrict__ pl, const float* __restrict__ anch,
    float* __restrict__ out)
{
    const unsigned g = blockIdx.x * 256u + threadIdx.x;
    if (g >= (unsigned)NR_TOT) return;        // whole-warp uniform (NR_TOT % 32 == 0)
    const int lane = threadIdx.x & 31;
    const unsigned warp_base = g & ~31u;

    // level selection — warp-uniform (boundaries are multiples of 32)
    const float* p; unsigned off, S3; float fS; int dect;
    if (warp_base < (unsigned)NR_S)            { p = ps; off = 0;            fS = 104.f; S3 = 312u;  dect = 3; }
    else if (warp_base < (unsigned)(NR_S+NR_M)){ p = pm; off = NR_S;         fS = 208.f; S3 = 624u;  dect = 4; }
    else                                       { p = pl; off = NR_S + NR_M;  fS = 416.f; S3 = 1248u; dect = 5; }

    const unsigned r_mine = g - off;
    const float conf = __ldg(p + (size_t)r_mine * 85u);
    unsigned mask = __ballot_sync(0xffffffffu, conf > 0.5f);
    if (!mask) return;                        // warp-uniform

    // warp-uniform precompute: one runtime division for the whole warp
    const unsigned rbase = warp_base - off;   // level-local row of lane 0
    const unsigned i0   = rbase / S3;
    const unsigned rem0 = rbase - i0 * S3;
    const float invS = 1.0f / fS;
    // preload the 3 anchors for this level (L1-resident after first warp)
    const float A0 = __ldg(anch + dect*6 + 0) * (1.0f/416.0f);
    const float A1 = __ldg(anch + dect*6 + 1) * (1.0f/416.0f);
    const float A2 = __ldg(anch + dect*6 + 2) * (1.0f/416.0f);
    const float A3 = __ldg(anch + dect*6 + 3) * (1.0f/416.0f);
    const float A4 = __ldg(anch + dect*6 + 4) * (1.0f/416.0f);
    const float A5 = __ldg(anch + dect*6 + 5) * (1.0f/416.0f);

    // ---- depth-2 software-pipelined cooperative decode of passing rows ----
    int src = __ffs(mask) - 1; mask &= mask - 1;
    float a0, a1, a2;
    {
        const float* row = p + (size_t)(rbase + src) * 85u;
        a0 = __ldg(row + lane);
        a1 = __ldg(row + 32 + lane);
        a2 = (lane < 21) ? __ldg(row + 64 + lane) : 0.0f;
    }

    while (src >= 0) {
        int nsrc = -1;
        float b0 = 0.f, b1 = 0.f, b2 = 0.f;
        if (mask) {
            nsrc = __ffs(mask) - 1; mask &= mask - 1;
            const float* row = p + (size_t)(rbase + nsrc) * 85u;
            b0 = __ldg(row + lane);
            b1 = __ldg(row + 32 + lane);
            b2 = (lane < 21) ? __ldg(row + 64 + lane) : 0.0f;
        }

        // ---- decode current row (lane `src` owns it) ----
        // per-lane argmax over class channels (>= 5), first-max semantics
        const unsigned m0 = mono_u32(a0), m1 = mono_u32(a1), m2 = mono_u32(a2);
        unsigned bm, bc;
        if (lane >= 5) { bm = m0; bc = lane;
                         if (m1 > bm) { bm = m1; bc = lane + 32; } }
        else           { bm = m1; bc = lane + 32; }
        if (lane < 21 && m2 > bm) { bm = m2; bc = lane + 64; }

        const unsigned M    = __reduce_max_sync(0xffffffffu, bm);
        const unsigned cand = (bm == M) ? bc : 0xffffffffu;
        const unsigned best = __reduce_min_sync(0xffffffffu, cand);

        const float cf = __shfl_sync(0xffffffffu, conf, src);
        const float tx = __shfl_sync(0xffffffffu, a0, 1);
        const float ty = __shfl_sync(0xffffffffu, a0, 2);
        const float tw = __shfl_sync(0xffffffffu, a0, 3);
        const float th = __shfl_sync(0xffffffffu, a0, 4);

        if (lane < 6) {
            const unsigned t  = rem0 + (unsigned)src;   // < S3 + 32
            const unsigned carry = (t >= S3) ? 1u : 0u;
            const unsigned i  = i0 + carry;
            const unsigned jA = t - (carry ? S3 : 0u);
            const unsigned j  = jA / 3u;                // const divisor: cheap
            const unsigned a  = jA - j * 3u;

            const float aw = (a == 0u) ? A0 : ((a == 1u) ? A2 : A4);
            const float ah = (a == 0u) ? A1 : ((a == 1u) ? A3 : A5);

            const float sx = 1.0f / (1.0f + __expf(-tx));
            const float sy = 1.0f / (1.0f + __expf(-ty));
            const float x = (sx + (float)i) * invS;
            const float y = (sy + (float)j) * invS;
            const float w = __expf(tw) * aw;
            const float h = __expf(th) * ah;

            float res;
            if      (lane == 0) res = x;
            else if (lane == 1) res = y;
            else if (lane == 2) res = w;
            else if (lane == 3) res = h;
            else if (lane == 4) res = (float)((int)best - 5);
            else                res = cf;
            out[(size_t)(warp_base + (unsigned)src) * 6u + lane] = res;
        }

        src = nsrc; a0 = b0; a1 = b1; a2 = b2;
    }
}

extern "C" void kernel_launch(void* const* d_in, const int* in_sizes, int n_in,
                              void* d_out, int out_size) {
    const float *ps = nullptr, *pm = nullptr, *pl = nullptr, *anch = nullptr;
    for (int k = 0; k < n_in; k++) {
        switch (in_sizes[k]) {
            case 104 * 104 * 3 * 85: ps   = (const float*)d_in[k]; break;
            case 208 * 208 * 3 * 85: pm   = (const float*)d_in[k]; break;
            case 416 * 416 * 3 * 85: pl   = (const float*)d_in[k]; break;
            case 36:                 anch = (const float*)d_in[k]; break;
            default: break;
        }
    }
    // zero the output (failing rows are never touched by the kernel)
    cudaMemsetAsync(d_out, 0, (size_t)out_size * sizeof(float));

    const int threads = 256;
    const int blocks = (NR_TOT + threads - 1) / threads;  // 2662
    yolo_decode_v2<<<blocks, threads>>>(ps, pm, pl, anch, (float*)d_out);
}